// round 14
// baseline (speedup 1.0000x reference)
#include <cuda_runtime.h>
#include <cuda_bf16.h>

// Problem constants
#define N_NODES   4000
#define NNODES    4001          // depot + nodes
#define EMBED     128
#define NC        25            // grid cells per dim (cell width = 0.04)
#define NCELLS    (NC * NC)     // 625
#define THRESH    0.04f
#define MAXS      384           // cap on 2-hop set size (expected ~80, max ~140)
#define MAXDEG    96            // cap on 1-hop degree (expected ~21, max ~50)
#define MAXCELL   32            // cap nodes per cell (expected 6.4, max ~22)
#define BMWORDS   128           // ceil(4001/32) = 126, padded to 128
#define FV2_T     128           // 4 warps per fv2 block
#define FV2_W     (FV2_T / 32)

// ---------------- device scratch (no allocations allowed) ----------------
__device__ float g_loc_x[NNODES];
__device__ float g_loc_y[NNODES];
__device__ float g_td[NNODES];
__device__ int   g_cell_count[NCELLS];
__device__ int   g_cell_nodes[NCELLS * MAXCELL];   // fixed stride, sorted by id
__device__ int   g_deg[NNODES];
__device__ int   g_nbr[NNODES * MAXDEG];
__device__ __align__(16) float g_fv1[NNODES * EMBED];

// ---------------- helpers ----------------
__device__ __forceinline__ int cell1d(float x) {
    int c = (int)(x * 25.0f);
    return min(NC - 1, max(0, c));
}

// Match reference: sqrt(dx*dx + dy*dy) <= 0.04f, no FMA contraction, IEEE sqrt.
__device__ __forceinline__ bool adj(float ax, float ay, float bx, float by) {
    float dx = __fadd_rn(ax, -bx);
    float dy = __fadd_rn(ay, -by);
    float d2 = __fadd_rn(__fmul_rn(dx, dx), __fmul_rn(dy, dy));
    return __fsqrt_rn(d2) <= THRESH;
}

// ---------------- setup: node arrays + zero cell counts ----------------
__global__ void __launch_bounds__(256) k_setup(const float* __restrict__ node_loc,
                                               const float* __restrict__ td,
                                               const float* __restrict__ depot) {
    int i = blockIdx.x * blockDim.x + threadIdx.x;
    if (i < NCELLS) g_cell_count[i] = 0;
    if (i >= NNODES) return;
    float x, y, d;
    if (i == 0) { x = depot[0]; y = depot[1]; d = 0.0f; }
    else        { x = node_loc[(i - 1) * 2 + 0]; y = node_loc[(i - 1) * 2 + 1]; d = td[i - 1]; }
    g_loc_x[i] = x; g_loc_y[i] = y; g_td[i] = d;
}

// ---------------- atomic scatter into fixed-stride cell segments ----------------
__global__ void __launch_bounds__(256) k_scatter() {
    int i = blockIdx.x * blockDim.x + threadIdx.x;
    if (i >= NNODES) return;
    int c = cell1d(g_loc_y[i]) * NC + cell1d(g_loc_x[i]);
    int pos = atomicAdd(&g_cell_count[c], 1);
    if (pos < MAXCELL) g_cell_nodes[c * MAXCELL + pos] = i;
}

// ---------------- per-cell warp bitonic sort (ascending id, deterministic) ----
__global__ void __launch_bounds__(256) k_sortcells() {
    int c    = (blockIdx.x * blockDim.x + threadIdx.x) >> 5;
    int lane = threadIdx.x & 31;
    if (c >= NCELLS) return;
    int raw = g_cell_count[c];
    int cnt = min(raw, MAXCELL);
    if (lane == 0 && raw > MAXCELL) g_cell_count[c] = MAXCELL;
    int val = (lane < cnt) ? g_cell_nodes[c * MAXCELL + lane] : 0x7FFFFFFF;
#pragma unroll
    for (int k = 2; k <= 32; k <<= 1) {
#pragma unroll
        for (int j = k >> 1; j > 0; j >>= 1) {
            int other = __shfl_xor_sync(0xffffffffu, val, j);
            bool dir   = ((lane & k) == 0);
            bool lower = ((lane & j) == 0);
            val = (lower == dir) ? min(val, other) : max(val, other);
        }
    }
    if (lane < cnt) g_cell_nodes[c * MAXCELL + lane] = val;
}

// ---------------- fused adjacency + fv_1 : one block (128 thr) per vertex ----
// All 4 warps test candidate cells concurrently; deterministic order via
// per-cell masks + serial 9-entry prefix (row-major cells, ascending id).
__global__ void __launch_bounds__(EMBED) k_adj_fv1(const float* __restrict__ W,
                                                   const float* __restrict__ b) {
    int v    = blockIdx.x;
    int tid  = threadIdx.x;
    int lane = tid & 31;
    int warp = tid >> 5;

    __shared__ unsigned s_mask[9];
    __shared__ int      s_pref[10];
    __shared__ int      s_candu[9 * 32];
    __shared__ float4   s_candf[9 * 32];      // (x, y, td, -)
    __shared__ int      s_nbr[MAXDEG];
    __shared__ float4   s_nf[MAXDEG];

    float vx = g_loc_x[v], vy = g_loc_y[v];
    int cx = cell1d(vx), cy = cell1d(vy);
    int x0 = max(0, cx - 1), x1 = min(NC - 1, cx + 1);
    int y0 = max(0, cy - 1), y1 = min(NC - 1, cy + 1);
    int nx = x1 - x0 + 1;
    int ncell = nx * (y1 - y0 + 1);

    // Phase 1: warp w tests cells j = w, w+4, w+8 (single ballot each)
    for (int j = warp; j < ncell; j += 4) {
        int c = (y0 + j / nx) * NC + (x0 + j % nx);
        int m = g_cell_count[c];
        bool val = false;
        int u = 0;
        float ux = 0.0f, uy = 0.0f, ut = 0.0f;
        if (lane < m) {
            u  = g_cell_nodes[c * MAXCELL + lane];   // coalesced
            ux = g_loc_x[u];
            uy = g_loc_y[u];
            ut = g_td[u];
            val = adj(vx, vy, ux, uy);
        }
        unsigned msk = __ballot_sync(0xffffffffu, val);
        s_candu[j * 32 + lane] = u;
        s_candf[j * 32 + lane] = make_float4(ux, uy, ut, 0.0f);
        if (lane == 0) s_mask[j] = msk;
    }
    __syncthreads();

    // Phase 2: serial prefix over <=9 cells (thread 0)
    if (tid == 0) {
        int acc = 0;
        for (int j = 0; j < ncell; j++) {
            s_pref[j] = acc;
            acc += __popc(s_mask[j]);
        }
        s_pref[ncell] = acc;
        g_deg[v] = min(acc, MAXDEG);
    }
    __syncthreads();
    int deg = min(s_pref[ncell], MAXDEG);

    // Phase 3: parallel mask-ranked compaction
    for (int j = warp; j < ncell; j += 4) {
        unsigned msk = s_mask[j];
        if ((msk >> lane) & 1u) {
            int pos = s_pref[j] + __popc(msk & ((1u << lane) - 1u));
            if (pos < MAXDEG) {
                s_nbr[pos] = s_candu[j * 32 + lane];
                s_nf[pos]  = s_candf[j * 32 + lane];
            }
        }
    }
    __syncthreads();

    // publish CSR row for fv2 (coalesced)
    if (tid < deg) g_nbr[v * MAXDEG + tid] = s_nbr[tid];

    // fv1: thread d owns output dim d; one LDS.128 per neighbor
    float w0 = W[tid * 3 + 0], w1 = W[tid * 3 + 1], w2 = W[tid * 3 + 2];
    float acc = 0.0f, bb = b[tid];
    for (int i = 0; i < deg; i++) {
        float4 n = s_nf[i];
        float f = fmaf(w2, n.z, fmaf(w1, n.y, fmaf(w0, n.x, bb)));
        acc += fmaxf(f, 0.0f);
    }
    g_fv1[v * EMBED + tid] = acc;
}

// ---------------- fv_2[v] = sum_{u in S(v)} c_u * fv_1[u] ----------------
// S(v) marked in a 4001-bit shared bitmap, enumerated via popc+scan (ascending id).
// c_u = |N(u) ∩ S(v)| warp-cooperative, single-round fast path (deg<=32 typical).
__global__ void __launch_bounds__(FV2_T) k_fv2(float* __restrict__ out) {
    int v    = blockIdx.x;
    int tid  = threadIdx.x;
    int lane = tid & 31;
    int warp = tid >> 5;

    __shared__ int      s_nbr[MAXDEG];
    __shared__ unsigned s_bm[BMWORDS];
    __shared__ int      s_sidx[MAXS];
    __shared__ float    s_c[MAXS];
    __shared__ int      s_wsum[FV2_W];
    __shared__ int      s_ns;
    __shared__ float4   s_acc[FV2_T];

    int deg = g_deg[v];

    s_bm[tid] = 0u;                                        // FV2_T == BMWORDS
    if (tid < deg) s_nbr[tid] = g_nbr[v * MAXDEG + tid];   // coalesced stage of N(v)
    __syncthreads();

    // --- Phase A: mark S = union of N(w), w in N(v). Single-round fast path. ---
    for (int i = warp; i < deg; i += FV2_W) {
        int w  = s_nbr[i];                    // smem broadcast
        int dw = g_deg[w];                    // broadcast
        const int* nw = &g_nbr[w * MAXDEG];
        if (lane < dw) {
            int u = nw[lane];                 // coalesced
            atomicOr(&s_bm[u >> 5], 1u << (u & 31));
        }
        for (int k = 32 + lane; k < dw; k += 32) {   // rare (deg > 32)
            int u = nw[k];
            atomicOr(&s_bm[u >> 5], 1u << (u & 31));
        }
    }
    __syncthreads();

    // --- Phase B: enumerate S from bitmap (popc + scan + bit extract) ---
    unsigned bw = s_bm[tid];
    int cnt = __popc(bw);
    int incl = cnt;
#pragma unroll
    for (int off = 1; off < 32; off <<= 1) {
        int n = __shfl_up_sync(0xffffffffu, incl, off);
        if (lane >= off) incl += n;
    }
    if (lane == 31) s_wsum[warp] = incl;
    __syncthreads();
    if (tid == 0) {                            // serial exclusive prefix over 4 warps
        int acc = 0;
#pragma unroll
        for (int wi = 0; wi < FV2_W; wi++) {
            int t = s_wsum[wi];
            s_wsum[wi] = acc;
            acc += t;
        }
        s_ns = min(acc, MAXS);
    }
    __syncthreads();
    int base = s_wsum[warp] + incl - cnt;      // exclusive prefix for this thread
    {
        int idx = tid << 5;
        unsigned w = bw;
        while (w) {
            int bpos = __ffs(w) - 1;
            if (base < MAXS) s_sidx[base] = idx + bpos;
            base++;
            w &= (w - 1);
        }
    }
    __syncthreads();
    int ns = s_ns;

    // --- Phase C: c_u = |N(u) ∩ S| — warp per u, single-round fast path ---
    for (int j = warp; j < ns; j += FV2_W) {
        int u  = s_sidx[j];
        int du = g_deg[u];                    // broadcast
        const int* nu = &g_nbr[u * MAXDEG];
        bool hit = false;
        if (lane < du) {
            int w = nu[lane];                 // coalesced
            hit = (s_bm[w >> 5] >> (w & 31)) & 1u;
        }
        int c = __popc(__ballot_sync(0xffffffffu, hit));
        for (int kb = 32; kb < du; kb += 32) {     // rare (deg > 32)
            int k = kb + lane;
            bool h2 = false;
            if (k < du) {
                int w = nu[k];
                h2 = (s_bm[w >> 5] >> (w & 31)) & 1u;
            }
            c += __popc(__ballot_sync(0xffffffffu, h2));
        }
        if (lane == 0) s_c[j] = (float)c;
    }
    __syncthreads();

    // --- Phase D: weighted float4 gather, unroll x2 (two independent accs) ---
    const float4* fv1 = (const float4*)g_fv1;
    float4 accA = make_float4(0.0f, 0.0f, 0.0f, 0.0f);
    float4 accB = make_float4(0.0f, 0.0f, 0.0f, 0.0f);
    int j = warp;
    for (; j + FV2_W < ns; j += 2 * FV2_W) {
        float  c0 = s_c[j];
        float  c1 = s_c[j + FV2_W];
        float4 r0 = fv1[s_sidx[j] * 32 + lane];
        float4 r1 = fv1[s_sidx[j + FV2_W] * 32 + lane];
        accA.x = fmaf(c0, r0.x, accA.x);
        accA.y = fmaf(c0, r0.y, accA.y);
        accA.z = fmaf(c0, r0.z, accA.z);
        accA.w = fmaf(c0, r0.w, accA.w);
        accB.x = fmaf(c1, r1.x, accB.x);
        accB.y = fmaf(c1, r1.y, accB.y);
        accB.z = fmaf(c1, r1.z, accB.z);
        accB.w = fmaf(c1, r1.w, accB.w);
    }
    if (j < ns) {
        float  c0 = s_c[j];
        float4 r0 = fv1[s_sidx[j] * 32 + lane];
        accA.x = fmaf(c0, r0.x, accA.x);
        accA.y = fmaf(c0, r0.y, accA.y);
        accA.z = fmaf(c0, r0.z, accA.z);
        accA.w = fmaf(c0, r0.w, accA.w);
    }
    // fixed combine order -> deterministic
    accA.x += accB.x; accA.y += accB.y; accA.z += accB.z; accA.w += accB.w;
    s_acc[tid] = accA;
    __syncthreads();

    // fixed-order 4-way reduce (deterministic), one 512B row store
    if (warp == 0) {
        float4 a0 = s_acc[lane];
        float4 a1 = s_acc[32 + lane];
        float4 a2 = s_acc[64 + lane];
        float4 a3 = s_acc[96 + lane];
        float4 r;
        r.x = (a0.x + a1.x) + (a2.x + a3.x);
        r.y = (a0.y + a1.y) + (a2.y + a3.y);
        r.z = (a0.z + a1.z) + (a2.z + a3.z);
        r.w = (a0.w + a1.w) + (a2.w + a3.w);
        ((float4*)out)[v * 32 + lane] = r;
    }
}

// ---------------- launch ----------------
extern "C" void kernel_launch(void* const* d_in, const int* in_sizes, int n_in,
                              void* d_out, int out_size) {
    const float* node_loc = (const float*)d_in[0];   // [4000, 2]
    const float* td       = (const float*)d_in[1];   // [4000, 1]
    const float* depot    = (const float*)d_in[2];   // [1, 2]
    const float* W0_w     = (const float*)d_in[3];   // [128, 3]
    const float* W0_b     = (const float*)d_in[4];   // [128]
    float* out = (float*)d_out;                      // [4001, 128]

    k_setup<<<(NNODES + 255) / 256, 256>>>(node_loc, td, depot);
    k_scatter<<<(NNODES + 255) / 256, 256>>>();
    k_sortcells<<<(NCELLS * 32 + 255) / 256, 256>>>();
    k_adj_fv1<<<NNODES, EMBED>>>(W0_w, W0_b);
    k_fv2<<<NNODES, FV2_T>>>(out);
}

// round 15
// speedup vs baseline: 1.0640x; 1.0640x over previous
#include <cuda_runtime.h>
#include <cuda_bf16.h>

// Problem constants
#define N_NODES   4000
#define NNODES    4001          // depot + nodes
#define EMBED     128
#define NC        25            // grid cells per dim (cell width = 0.04)
#define NCELLS    (NC * NC)     // 625
#define THRESH    0.04f
#define MAXS      384           // cap on 2-hop set size (expected ~80, max ~140)
#define MAXDEG    96            // cap on 1-hop degree (expected ~21, max ~50)
#define MAXCELL   32            // cap nodes per cell (expected 6.4, max ~22)
#define BMWORDS   128           // ceil(4001/32) = 126, padded to 128
#define FV2_T     128           // 4 warps per fv2 block
#define FV2_W     (FV2_T / 32)

// ---------------- device scratch (no allocations allowed) ----------------
// g_cell_count is zero-initialized at load; every kernel_launch leaves it
// zeroed again (tail of k_fv2), keeping graph replays deterministic.
__device__ float g_loc_x[NNODES];
__device__ float g_loc_y[NNODES];
__device__ float g_td[NNODES];
__device__ int   g_cell_count[NCELLS];
__device__ int   g_cell_nodes[NCELLS * MAXCELL];            // sorted by id
__device__ __align__(16) float4 g_cell_f4[NCELLS * MAXCELL]; // (x,y,td,id)
__device__ int   g_deg[NNODES];
__device__ int   g_nbr[NNODES * MAXDEG];
__device__ __align__(16) float g_fv1[NNODES * EMBED];

// ---------------- helpers ----------------
__device__ __forceinline__ int cell1d(float x) {
    int c = (int)(x * 25.0f);
    return min(NC - 1, max(0, c));
}

// Match reference: sqrt(dx*dx + dy*dy) <= 0.04f, no FMA contraction, IEEE sqrt.
__device__ __forceinline__ bool adj(float ax, float ay, float bx, float by) {
    float dx = __fadd_rn(ax, -bx);
    float dy = __fadd_rn(ay, -by);
    float d2 = __fadd_rn(__fmul_rn(dx, dx), __fmul_rn(dy, dy));
    return __fsqrt_rn(d2) <= THRESH;
}

// ---------------- fused setup + atomic scatter ----------------
__global__ void __launch_bounds__(256) k_scatter(const float* __restrict__ node_loc,
                                                 const float* __restrict__ td,
                                                 const float* __restrict__ depot) {
    int i = blockIdx.x * blockDim.x + threadIdx.x;
    if (i >= NNODES) return;
    float x, y, d;
    if (i == 0) { x = depot[0]; y = depot[1]; d = 0.0f; }
    else        { x = node_loc[(i - 1) * 2 + 0]; y = node_loc[(i - 1) * 2 + 1]; d = td[i - 1]; }
    g_loc_x[i] = x; g_loc_y[i] = y; g_td[i] = d;
    int c = cell1d(y) * NC + cell1d(x);
    int pos = atomicAdd(&g_cell_count[c], 1);           // counts pre-zeroed
    if (pos < MAXCELL) g_cell_nodes[c * MAXCELL + pos] = i;
}

// ---------------- per-cell warp bitonic sort + packed coordinate table ----
__global__ void __launch_bounds__(256) k_sortcells() {
    int c    = (blockIdx.x * blockDim.x + threadIdx.x) >> 5;
    int lane = threadIdx.x & 31;
    if (c >= NCELLS) return;
    int raw = g_cell_count[c];
    int cnt = min(raw, MAXCELL);
    if (lane == 0 && raw > MAXCELL) g_cell_count[c] = MAXCELL;
    int val = (lane < cnt) ? g_cell_nodes[c * MAXCELL + lane] : 0x7FFFFFFF;
#pragma unroll
    for (int k = 2; k <= 32; k <<= 1) {
#pragma unroll
        for (int j = k >> 1; j > 0; j >>= 1) {
            int other = __shfl_xor_sync(0xffffffffu, val, j);
            bool dir   = ((lane & k) == 0);
            bool lower = ((lane & j) == 0);
            val = (lower == dir) ? min(val, other) : max(val, other);
        }
    }
    if (lane < cnt) {
        g_cell_nodes[c * MAXCELL + lane] = val;
        g_cell_f4[c * MAXCELL + lane] =
            make_float4(g_loc_x[val], g_loc_y[val], g_td[val], __int_as_float(val));
    }
}

// ---------------- fused adjacency + fv_1 : one block (128 thr) per vertex ----
// One coalesced LDG.128 per candidate (coords+id packed). Deterministic order
// via per-cell masks + serial 9-entry prefix (row-major cells, ascending id).
__global__ void __launch_bounds__(EMBED) k_adj_fv1(const float* __restrict__ W,
                                                   const float* __restrict__ b) {
    int v    = blockIdx.x;
    int tid  = threadIdx.x;
    int lane = tid & 31;
    int warp = tid >> 5;

    __shared__ unsigned s_mask[9];
    __shared__ int      s_pref[10];
    __shared__ float4   s_candf[9 * 32];      // (x, y, td, id)
    __shared__ float4   s_nf[MAXDEG];

    float vx = g_loc_x[v], vy = g_loc_y[v];
    int cx = cell1d(vx), cy = cell1d(vy);
    int x0 = max(0, cx - 1), x1 = min(NC - 1, cx + 1);
    int y0 = max(0, cy - 1), y1 = min(NC - 1, cy + 1);
    int nx = x1 - x0 + 1;
    int ncell = nx * (y1 - y0 + 1);

    // Phase 1: warp w tests cells j = w, w+4, w+8 (one LDG.128 + one ballot)
    for (int j = warp; j < ncell; j += 4) {
        int c = (y0 + j / nx) * NC + (x0 + j % nx);
        int m = g_cell_count[c];
        bool val = false;
        float4 f = make_float4(0.0f, 0.0f, 0.0f, 0.0f);
        if (lane < m) {
            f = g_cell_f4[c * MAXCELL + lane];   // coalesced 128-bit
            val = adj(vx, vy, f.x, f.y);
        }
        unsigned msk = __ballot_sync(0xffffffffu, val);
        s_candf[j * 32 + lane] = f;
        if (lane == 0) s_mask[j] = msk;
    }
    __syncthreads();

    // Phase 2: serial prefix over <=9 cells (thread 0)
    if (tid == 0) {
        int acc = 0;
        for (int j = 0; j < ncell; j++) {
            s_pref[j] = acc;
            acc += __popc(s_mask[j]);
        }
        s_pref[ncell] = acc;
        g_deg[v] = min(acc, MAXDEG);
    }
    __syncthreads();
    int deg = min(s_pref[ncell], MAXDEG);

    // Phase 3: parallel mask-ranked compaction
    for (int j = warp; j < ncell; j += 4) {
        unsigned msk = s_mask[j];
        if ((msk >> lane) & 1u) {
            int pos = s_pref[j] + __popc(msk & ((1u << lane) - 1u));
            if (pos < MAXDEG) s_nf[pos] = s_candf[j * 32 + lane];
        }
    }
    __syncthreads();

    // publish CSR row for fv2 (coalesced)
    if (tid < deg) g_nbr[v * MAXDEG + tid] = __float_as_int(s_nf[tid].w);

    // fv1: thread d owns output dim d; one LDS.128 per neighbor
    float w0 = W[tid * 3 + 0], w1 = W[tid * 3 + 1], w2 = W[tid * 3 + 2];
    float acc = 0.0f, bb = b[tid];
    for (int i = 0; i < deg; i++) {
        float4 n = s_nf[i];
        float f = fmaf(w2, n.z, fmaf(w1, n.y, fmaf(w0, n.x, bb)));
        acc += fmaxf(f, 0.0f);
    }
    g_fv1[v * EMBED + tid] = acc;
}

// ---------------- fv_2[v] = sum_{u in S(v)} c_u * fv_1[u] ----------------
// S(v) marked in a 4001-bit shared bitmap, enumerated via popc+scan (ascending id).
// c_u = |N(u) ∩ S(v)| warp-cooperative, single-round fast path (deg<=32 typical).
__global__ void __launch_bounds__(FV2_T) k_fv2(float* __restrict__ out) {
    int v    = blockIdx.x;
    int tid  = threadIdx.x;
    int lane = tid & 31;
    int warp = tid >> 5;

    __shared__ int      s_nbr[MAXDEG];
    __shared__ unsigned s_bm[BMWORDS];
    __shared__ int      s_sidx[MAXS];
    __shared__ float    s_c[MAXS];
    __shared__ int      s_wsum[FV2_W];
    __shared__ int      s_ns;
    __shared__ float4   s_acc[FV2_T];

    // re-zero cell counts for the next graph replay (nothing reads them
    // again until the next launch sequence's k_scatter)
    if (v == 0) {
        for (int i = tid; i < NCELLS; i += FV2_T) g_cell_count[i] = 0;
    }

    int deg = g_deg[v];

    s_bm[tid] = 0u;                                        // FV2_T == BMWORDS
    if (tid < deg) s_nbr[tid] = g_nbr[v * MAXDEG + tid];   // coalesced stage of N(v)
    __syncthreads();

    // --- Phase A: mark S = union of N(w), w in N(v). Single-round fast path. ---
    for (int i = warp; i < deg; i += FV2_W) {
        int w  = s_nbr[i];                    // smem broadcast
        int dw = g_deg[w];                    // broadcast
        const int* nw = &g_nbr[w * MAXDEG];
        if (lane < dw) {
            int u = nw[lane];                 // coalesced
            atomicOr(&s_bm[u >> 5], 1u << (u & 31));
        }
        for (int k = 32 + lane; k < dw; k += 32) {   // rare (deg > 32)
            int u = nw[k];
            atomicOr(&s_bm[u >> 5], 1u << (u & 31));
        }
    }
    __syncthreads();

    // --- Phase B: enumerate S from bitmap (popc + scan + bit extract) ---
    unsigned bw = s_bm[tid];
    int cnt = __popc(bw);
    int incl = cnt;
#pragma unroll
    for (int off = 1; off < 32; off <<= 1) {
        int n = __shfl_up_sync(0xffffffffu, incl, off);
        if (lane >= off) incl += n;
    }
    if (lane == 31) s_wsum[warp] = incl;
    __syncthreads();
    if (tid == 0) {                            // serial exclusive prefix over 4 warps
        int acc = 0;
#pragma unroll
        for (int wi = 0; wi < FV2_W; wi++) {
            int t = s_wsum[wi];
            s_wsum[wi] = acc;
            acc += t;
        }
        s_ns = min(acc, MAXS);
    }
    __syncthreads();
    int base = s_wsum[warp] + incl - cnt;      // exclusive prefix for this thread
    {
        int idx = tid << 5;
        unsigned w = bw;
        while (w) {
            int bpos = __ffs(w) - 1;
            if (base < MAXS) s_sidx[base] = idx + bpos;
            base++;
            w &= (w - 1);
        }
    }
    __syncthreads();
    int ns = s_ns;

    // --- Phase C: c_u = |N(u) ∩ S| — warp per u, single-round fast path ---
    for (int j = warp; j < ns; j += FV2_W) {
        int u  = s_sidx[j];
        int du = g_deg[u];                    // broadcast
        const int* nu = &g_nbr[u * MAXDEG];
        bool hit = false;
        if (lane < du) {
            int w = nu[lane];                 // coalesced
            hit = (s_bm[w >> 5] >> (w & 31)) & 1u;
        }
        int c = __popc(__ballot_sync(0xffffffffu, hit));
        for (int kb = 32; kb < du; kb += 32) {     // rare (deg > 32)
            int k = kb + lane;
            bool h2 = false;
            if (k < du) {
                int w = nu[k];
                h2 = (s_bm[w >> 5] >> (w & 31)) & 1u;
            }
            c += __popc(__ballot_sync(0xffffffffu, h2));
        }
        if (lane == 0) s_c[j] = (float)c;
    }
    __syncthreads();

    // --- Phase D: weighted float4 gather, unroll x2 (two independent accs) ---
    const float4* fv1 = (const float4*)g_fv1;
    float4 accA = make_float4(0.0f, 0.0f, 0.0f, 0.0f);
    float4 accB = make_float4(0.0f, 0.0f, 0.0f, 0.0f);
    int j = warp;
    for (; j + FV2_W < ns; j += 2 * FV2_W) {
        float  c0 = s_c[j];
        float  c1 = s_c[j + FV2_W];
        float4 r0 = fv1[s_sidx[j] * 32 + lane];
        float4 r1 = fv1[s_sidx[j + FV2_W] * 32 + lane];
        accA.x = fmaf(c0, r0.x, accA.x);
        accA.y = fmaf(c0, r0.y, accA.y);
        accA.z = fmaf(c0, r0.z, accA.z);
        accA.w = fmaf(c0, r0.w, accA.w);
        accB.x = fmaf(c1, r1.x, accB.x);
        accB.y = fmaf(c1, r1.y, accB.y);
        accB.z = fmaf(c1, r1.z, accB.z);
        accB.w = fmaf(c1, r1.w, accB.w);
    }
    if (j < ns) {
        float  c0 = s_c[j];
        float4 r0 = fv1[s_sidx[j] * 32 + lane];
        accA.x = fmaf(c0, r0.x, accA.x);
        accA.y = fmaf(c0, r0.y, accA.y);
        accA.z = fmaf(c0, r0.z, accA.z);
        accA.w = fmaf(c0, r0.w, accA.w);
    }
    // fixed combine order -> deterministic
    accA.x += accB.x; accA.y += accB.y; accA.z += accB.z; accA.w += accB.w;
    s_acc[tid] = accA;
    __syncthreads();

    // fixed-order 4-way reduce (deterministic), one 512B row store
    if (warp == 0) {
        float4 a0 = s_acc[lane];
        float4 a1 = s_acc[32 + lane];
        float4 a2 = s_acc[64 + lane];
        float4 a3 = s_acc[96 + lane];
        float4 r;
        r.x = (a0.x + a1.x) + (a2.x + a3.x);
        r.y = (a0.y + a1.y) + (a2.y + a3.y);
        r.z = (a0.z + a1.z) + (a2.z + a3.z);
        r.w = (a0.w + a1.w) + (a2.w + a3.w);
        ((float4*)out)[v * 32 + lane] = r;
    }
}

// ---------------- launch ----------------
extern "C" void kernel_launch(void* const* d_in, const int* in_sizes, int n_in,
                              void* d_out, int out_size) {
    const float* node_loc = (const float*)d_in[0];   // [4000, 2]
    const float* td       = (const float*)d_in[1];   // [4000, 1]
    const float* depot    = (const float*)d_in[2];   // [1, 2]
    const float* W0_w     = (const float*)d_in[3];   // [128, 3]
    const float* W0_b     = (const float*)d_in[4];   // [128]
    float* out = (float*)d_out;                      // [4001, 128]

    k_scatter<<<(NNODES + 255) / 256, 256>>>(node_loc, td, depot);
    k_sortcells<<<(NCELLS * 32 + 255) / 256, 256>>>();
    k_adj_fv1<<<NNODES, EMBED>>>(W0_w, W0_b);
    k_fv2<<<NNODES, FV2_T>>>(out);
}

// round 16
// speedup vs baseline: 1.2605x; 1.1847x over previous
#include <cuda_runtime.h>
#include <cuda_bf16.h>

// Problem constants
#define N_NODES   4000
#define NNODES    4001          // depot + nodes
#define EMBED     128
#define NC        25            // grid cells per dim (cell width = 0.04)
#define NCELLS    (NC * NC)     // 625
#define THRESH    0.04f
#define MAXS      384           // cap on 2-hop set size (expected ~80, max ~140)
#define MAXDEG    96            // cap on 1-hop degree (expected ~21, max ~50)
#define MAXCELL   32            // cap nodes per cell (expected 6.4, max ~22)
#define BMWORDS   128           // ceil(4001/32) = 126, padded to 128
#define FV2_T     128           // 4 warps per fv2 block
#define FV2_W     (FV2_T / 32)

// ---------------- device scratch (no allocations allowed) ----------------
// g_cell_count is zero-initialized at load; every kernel_launch leaves it
// zeroed again (tail of k_fv2), keeping graph replays deterministic.
__device__ float g_loc_x[NNODES];
__device__ float g_loc_y[NNODES];
__device__ float g_td[NNODES];
__device__ int   g_cell_count[NCELLS];
__device__ int   g_cell_nodes[NCELLS * MAXCELL];            // sorted by id
__device__ __align__(16) float4 g_cell_f4[NCELLS * MAXCELL]; // (x,y,td,id)
__device__ int   g_deg[NNODES];
__device__ int   g_nbr[NNODES * MAXDEG];
__device__ __align__(16) float g_fv1[NNODES * EMBED];

// ---------------- helpers ----------------
__device__ __forceinline__ int cell1d(float x) {
    int c = (int)(x * 25.0f);
    return min(NC - 1, max(0, c));
}

// Match reference: sqrt(dx*dx + dy*dy) <= 0.04f, no FMA contraction, IEEE sqrt.
__device__ __forceinline__ bool adj(float ax, float ay, float bx, float by) {
    float dx = __fadd_rn(ax, -bx);
    float dy = __fadd_rn(ay, -by);
    float d2 = __fadd_rn(__fmul_rn(dx, dx), __fmul_rn(dy, dy));
    return __fsqrt_rn(d2) <= THRESH;
}

// ---------------- fused setup + atomic scatter ----------------
__global__ void __launch_bounds__(256) k_scatter(const float* __restrict__ node_loc,
                                                 const float* __restrict__ td,
                                                 const float* __restrict__ depot) {
    int i = blockIdx.x * blockDim.x + threadIdx.x;
    if (i >= NNODES) return;
    float x, y, d;
    if (i == 0) { x = depot[0]; y = depot[1]; d = 0.0f; }
    else        { x = node_loc[(i - 1) * 2 + 0]; y = node_loc[(i - 1) * 2 + 1]; d = td[i - 1]; }
    g_loc_x[i] = x; g_loc_y[i] = y; g_td[i] = d;
    int c = cell1d(y) * NC + cell1d(x);
    int pos = atomicAdd(&g_cell_count[c], 1);           // counts pre-zeroed
    if (pos < MAXCELL) g_cell_nodes[c * MAXCELL + pos] = i;
}

// ---------------- per-cell warp bitonic sort + packed coordinate table ----
__global__ void __launch_bounds__(256) k_sortcells() {
    int c    = (blockIdx.x * blockDim.x + threadIdx.x) >> 5;
    int lane = threadIdx.x & 31;
    if (c >= NCELLS) return;
    int raw = g_cell_count[c];
    int cnt = min(raw, MAXCELL);
    if (lane == 0 && raw > MAXCELL) g_cell_count[c] = MAXCELL;
    int val = (lane < cnt) ? g_cell_nodes[c * MAXCELL + lane] : 0x7FFFFFFF;
#pragma unroll
    for (int k = 2; k <= 32; k <<= 1) {
#pragma unroll
        for (int j = k >> 1; j > 0; j >>= 1) {
            int other = __shfl_xor_sync(0xffffffffu, val, j);
            bool dir   = ((lane & k) == 0);
            bool lower = ((lane & j) == 0);
            val = (lower == dir) ? min(val, other) : max(val, other);
        }
    }
    if (lane < cnt) {
        g_cell_nodes[c * MAXCELL + lane] = val;
        g_cell_f4[c * MAXCELL + lane] =
            make_float4(g_loc_x[val], g_loc_y[val], g_td[val], __int_as_float(val));
    }
}

// ---------------- fused adjacency + fv_1 : one block (128 thr) per vertex ----
// One coalesced LDG.128 per candidate (coords+id packed). Deterministic order
// via per-cell masks + serial 9-entry prefix (row-major cells, ascending id).
__global__ void __launch_bounds__(EMBED) k_adj_fv1(const float* __restrict__ W,
                                                   const float* __restrict__ b) {
    int v    = blockIdx.x;
    int tid  = threadIdx.x;
    int lane = tid & 31;
    int warp = tid >> 5;

    __shared__ unsigned s_mask[9];
    __shared__ int      s_pref[10];
    __shared__ float4   s_candf[9 * 32];      // (x, y, td, id)
    __shared__ float4   s_nf[MAXDEG];

    float vx = g_loc_x[v], vy = g_loc_y[v];
    int cx = cell1d(vx), cy = cell1d(vy);
    int x0 = max(0, cx - 1), x1 = min(NC - 1, cx + 1);
    int y0 = max(0, cy - 1), y1 = min(NC - 1, cy + 1);
    int nx = x1 - x0 + 1;
    int ncell = nx * (y1 - y0 + 1);

    // Phase 1: warp w tests cells j = w, w+4, w+8 (one LDG.128 + one ballot)
    for (int j = warp; j < ncell; j += 4) {
        int c = (y0 + j / nx) * NC + (x0 + j % nx);
        int m = g_cell_count[c];
        bool val = false;
        float4 f = make_float4(0.0f, 0.0f, 0.0f, 0.0f);
        if (lane < m) {
            f = g_cell_f4[c * MAXCELL + lane];   // coalesced 128-bit
            val = adj(vx, vy, f.x, f.y);
        }
        unsigned msk = __ballot_sync(0xffffffffu, val);
        s_candf[j * 32 + lane] = f;
        if (lane == 0) s_mask[j] = msk;
    }
    __syncthreads();

    // Phase 2: serial prefix over <=9 cells (thread 0)
    if (tid == 0) {
        int acc = 0;
        for (int j = 0; j < ncell; j++) {
            s_pref[j] = acc;
            acc += __popc(s_mask[j]);
        }
        s_pref[ncell] = acc;
        g_deg[v] = min(acc, MAXDEG);
    }
    __syncthreads();
    int deg = min(s_pref[ncell], MAXDEG);

    // Phase 3: parallel mask-ranked compaction
    for (int j = warp; j < ncell; j += 4) {
        unsigned msk = s_mask[j];
        if ((msk >> lane) & 1u) {
            int pos = s_pref[j] + __popc(msk & ((1u << lane) - 1u));
            if (pos < MAXDEG) s_nf[pos] = s_candf[j * 32 + lane];
        }
    }
    __syncthreads();

    // publish CSR row for fv2 (coalesced)
    if (tid < deg) g_nbr[v * MAXDEG + tid] = __float_as_int(s_nf[tid].w);

    // fv1: thread d owns output dim d; one LDS.128 per neighbor
    float w0 = W[tid * 3 + 0], w1 = W[tid * 3 + 1], w2 = W[tid * 3 + 2];
    float acc = 0.0f, bb = b[tid];
    for (int i = 0; i < deg; i++) {
        float4 n = s_nf[i];
        float f = fmaf(w2, n.z, fmaf(w1, n.y, fmaf(w0, n.x, bb)));
        acc += fmaxf(f, 0.0f);
    }
    g_fv1[v * EMBED + tid] = acc;
}

// ---------------- fv_2[v] = sum_{u in S(v)} c_u * fv_1[u] ----------------
// S(v) in a 4001-bit shared bitmap; enumerate ascending; degrees prefetched to
// smem; Phase C (count ballot) fused into Phase D (gather) so the independent
// fv1 LDG.128 overlaps the adjacency-test chain.
__global__ void __launch_bounds__(FV2_T) k_fv2(float* __restrict__ out) {
    int v    = blockIdx.x;
    int tid  = threadIdx.x;
    int lane = tid & 31;
    int warp = tid >> 5;

    __shared__ int      s_nbr[MAXDEG];
    __shared__ int      s_ndeg[MAXDEG];
    __shared__ unsigned s_bm[BMWORDS];
    __shared__ int      s_sidx[MAXS];
    __shared__ int      s_du[MAXS];
    __shared__ int      s_wsum[FV2_W];
    __shared__ int      s_ns;
    __shared__ float4   s_acc[FV2_T];

    // re-zero cell counts for the next graph replay (nothing reads them
    // again until the next launch sequence's k_scatter)
    if (v == 0) {
        for (int i = tid; i < NCELLS; i += FV2_T) g_cell_count[i] = 0;
    }

    int deg = g_deg[v];

    s_bm[tid] = 0u;                                        // FV2_T == BMWORDS
    if (tid < deg) {
        int w = g_nbr[v * MAXDEG + tid];                   // coalesced
        s_nbr[tid]  = w;
        s_ndeg[tid] = g_deg[w];                            // parallel scattered
    }
    __syncthreads();

    // --- Phase A: mark S = union of N(w), w in N(v). Single-round fast path. ---
    for (int i = warp; i < deg; i += FV2_W) {
        int w  = s_nbr[i];                    // smem broadcast
        int dw = s_ndeg[i];                   // smem broadcast (prefetched)
        const int* nw = &g_nbr[w * MAXDEG];
        if (lane < dw) {
            int u = nw[lane];                 // coalesced
            atomicOr(&s_bm[u >> 5], 1u << (u & 31));
        }
        for (int k = 32 + lane; k < dw; k += 32) {   // rare (deg > 32)
            int u = nw[k];
            atomicOr(&s_bm[u >> 5], 1u << (u & 31));
        }
    }
    __syncthreads();

    // --- Phase B: enumerate S from bitmap (popc + scan + bit extract) ---
    unsigned bw = s_bm[tid];
    int cnt = __popc(bw);
    int incl = cnt;
#pragma unroll
    for (int off = 1; off < 32; off <<= 1) {
        int n = __shfl_up_sync(0xffffffffu, incl, off);
        if (lane >= off) incl += n;
    }
    if (lane == 31) s_wsum[warp] = incl;
    __syncthreads();
    if (tid == 0) {                            // serial exclusive prefix over 4 warps
        int acc = 0;
#pragma unroll
        for (int wi = 0; wi < FV2_W; wi++) {
            int t = s_wsum[wi];
            s_wsum[wi] = acc;
            acc += t;
        }
        s_ns = min(acc, MAXS);
    }
    __syncthreads();
    int base = s_wsum[warp] + incl - cnt;      // exclusive prefix for this thread
    {
        int idx = tid << 5;
        unsigned w = bw;
        while (w) {
            int bpos = __ffs(w) - 1;
            if (base < MAXS) s_sidx[base] = idx + bpos;
            base++;
            w &= (w - 1);
        }
    }
    __syncthreads();
    int ns = s_ns;

    // prefetch degrees of S members (parallel scattered, full MLP)
    for (int j = tid; j < ns; j += FV2_T) s_du[j] = g_deg[s_sidx[j]];
    __syncthreads();

    // --- fused Phase C+D: per u, ballot-count c_u while fv1 row load flies ---
    const float4* fv1 = (const float4*)g_fv1;
    float4 acc = make_float4(0.0f, 0.0f, 0.0f, 0.0f);
    for (int j = warp; j < ns; j += FV2_W) {
        int u  = s_sidx[j];
        int du = s_du[j];                      // smem (prefetched)
        const int* nu = &g_nbr[u * MAXDEG];
        float4 r = fv1[u * 32 + lane];         // independent of ballot chain
        bool hit = false;
        if (lane < du) {
            int w = nu[lane];                  // coalesced
            hit = (s_bm[w >> 5] >> (w & 31)) & 1u;
        }
        int c = __popc(__ballot_sync(0xffffffffu, hit));
        for (int kb = 32; kb < du; kb += 32) { // rare (deg > 32)
            int k = kb + lane;
            bool h2 = false;
            if (k < du) {
                int w = nu[k];
                h2 = (s_bm[w >> 5] >> (w & 31)) & 1u;
            }
            c += __popc(__ballot_sync(0xffffffffu, h2));
        }
        float cf = (float)c;                   // exact integer
        acc.x = fmaf(cf, r.x, acc.x);
        acc.y = fmaf(cf, r.y, acc.y);
        acc.z = fmaf(cf, r.z, acc.z);
        acc.w = fmaf(cf, r.w, acc.w);
    }
    s_acc[tid] = acc;
    __syncthreads();

    // fixed-order 4-way reduce (deterministic), one 512B row store
    if (warp == 0) {
        float4 a0 = s_acc[lane];
        float4 a1 = s_acc[32 + lane];
        float4 a2 = s_acc[64 + lane];
        float4 a3 = s_acc[96 + lane];
        float4 r;
        r.x = (a0.x + a1.x) + (a2.x + a3.x);
        r.y = (a0.y + a1.y) + (a2.y + a3.y);
        r.z = (a0.z + a1.z) + (a2.z + a3.z);
        r.w = (a0.w + a1.w) + (a2.w + a3.w);
        ((float4*)out)[v * 32 + lane] = r;
    }
}

// ---------------- launch ----------------
extern "C" void kernel_launch(void* const* d_in, const int* in_sizes, int n_in,
                              void* d_out, int out_size) {
    const float* node_loc = (const float*)d_in[0];   // [4000, 2]
    const float* td       = (const float*)d_in[1];   // [4000, 1]
    const float* depot    = (const float*)d_in[2];   // [1, 2]
    const float* W0_w     = (const float*)d_in[3];   // [128, 3]
    const float* W0_b     = (const float*)d_in[4];   // [128]
    float* out = (float*)d_out;                      // [4001, 128]

    k_scatter<<<(NNODES + 255) / 256, 256>>>(node_loc, td, depot);
    k_sortcells<<<(NCELLS * 32 + 255) / 256, 256>>>();
    k_adj_fv1<<<NNODES, EMBED>>>(W0_w, W0_b);
    k_fv2<<<NNODES, FV2_T>>>(out);
}